// round 7
// baseline (speedup 1.0000x reference)
#include <cuda_runtime.h>
#include <cstdint>

#define B 64
#define T 50
#define D 512
#define H 1024
#define V 32000
#define G3 3072   // 3*H

// ---------------- scratch (no allocations allowed) ----------------
__device__ float g_h[B * H];
__device__ float g_gi[B * G3];
__device__ float g_gh[B * G3];
__device__ unsigned long long g_packed[B];

// ---------------- packed f32x2 helpers (sm_100a) ----------------
__device__ __forceinline__ void fma2(unsigned long long& d, unsigned long long a, unsigned long long b) {
    asm("fma.rn.f32x2 %0, %1, %2, %0;" : "+l"(d) : "l"(a), "l"(b));
}
__device__ __forceinline__ unsigned long long pack2(float x, float y) {
    unsigned long long r; asm("mov.b64 %0, {%1, %2};" : "=l"(r) : "f"(x), "f"(y)); return r;
}
__device__ __forceinline__ float2 unpack2(unsigned long long v) {
    float2 r; asm("mov.b64 {%0, %1}, %2;" : "=f"(r.x), "=f"(r.y) : "l"(v)); return r;
}

// ---------------- threefry2x32 (exact JAX rotation/key schedule) ----------------
__device__ __forceinline__ void tf2x32(uint32_t k0, uint32_t k1, uint32_t x0, uint32_t x1,
                                       uint32_t& o0, uint32_t& o1) {
    uint32_t ks2 = k0 ^ k1 ^ 0x1BD11BDAu;
    x0 += k0; x1 += k1;
#define RND(r) { x0 += x1; x1 = __funnelshift_l(x1, x1, (r)); x1 ^= x0; }
    RND(13) RND(15) RND(26) RND(6)   x0 += k1;  x1 += ks2 + 1u;
    RND(17) RND(29) RND(16) RND(24)  x0 += ks2; x1 += k0  + 2u;
    RND(13) RND(15) RND(26) RND(6)   x0 += k0;  x1 += k1  + 3u;
    RND(17) RND(29) RND(16) RND(24)  x0 += k1;  x1 += ks2 + 4u;
    RND(13) RND(15) RND(26) RND(6)   x0 += ks2; x1 += k0  + 5u;
#undef RND
    o0 = x0; o1 = x1;
}

static inline uint32_t h_rotl(uint32_t v, int d) { return (v << d) | (v >> (32 - d)); }
static void tf2x32_host(uint32_t k0, uint32_t k1, uint32_t x0, uint32_t x1,
                        uint32_t* o0, uint32_t* o1) {
    uint32_t ks2 = k0 ^ k1 ^ 0x1BD11BDAu;
    const int rA[4] = {13, 15, 26, 6}, rB[4] = {17, 29, 16, 24};
    x0 += k0; x1 += k1;
    for (int i = 0; i < 4; i++) { x0 += x1; x1 = h_rotl(x1, rA[i]); x1 ^= x0; }
    x0 += k1;  x1 += ks2 + 1u;
    for (int i = 0; i < 4; i++) { x0 += x1; x1 = h_rotl(x1, rB[i]); x1 ^= x0; }
    x0 += ks2; x1 += k0 + 2u;
    for (int i = 0; i < 4; i++) { x0 += x1; x1 = h_rotl(x1, rA[i]); x1 ^= x0; }
    x0 += k0;  x1 += k1 + 3u;
    for (int i = 0; i < 4; i++) { x0 += x1; x1 = h_rotl(x1, rB[i]); x1 ^= x0; }
    x0 += k1;  x1 += ks2 + 4u;
    for (int i = 0; i < 4; i++) { x0 += x1; x1 = h_rotl(x1, rA[i]); x1 ^= x0; }
    x0 += ks2; x1 += k0 + 5u;
    *o0 = x0; *o1 = x1;
}

// ============================================================================
// GRU gemm v2: gi = x@Wih^T, gh = h@Whh^T. Grid 96 x 512 threads.
// Block tile: 64 b x 32 g. K chunks of 32 (16 x-chunks, 32 h-chunks).
// Double-buffered smem; W stored duplicated as u64 (no inner-loop packs).
// Inner loop per kk: 1 LDS.64 (b-pair) + 1 LDS.128 (2 dup'd w) + 2 FMA2.
// Block 0 also writes out sampled indices of step t-1.
// ============================================================================
__global__ void __launch_bounds__(512) gru_gemm_kernel(
    int t, const float* __restrict__ seq_emb, const float* __restrict__ emb,
    const float* __restrict__ Wih, const float* __restrict__ Whh,
    const int* __restrict__ eosp, float* __restrict__ out)
{
    __shared__ float sA[2][32][66];
    __shared__ unsigned long long sWd[2][32][34];
    __shared__ int sIdx[B];
    int tid = threadIdx.x;
    int g0 = blockIdx.x * 32;

    if (tid < B) {
        int idx;
        if (t == 0) idx = eosp[0];
        else idx = (int)(0x7FFFFFFFu - (unsigned)(g_packed[tid] & 0xFFFFFFFFull));
        sIdx[tid] = idx;
        if (blockIdx.x == 0 && t > 0) out[(t - 1) * B + tid] = (float)idx;
    }
    __syncthreads();

    const float* hin = (t == 0) ? seq_emb : g_h;

    // load-phase mapping
    int a_b  = tid >> 3, a_kq = tid & 7;    // A: b row, float4 at k = a_kq*4
    int w_g  = tid >> 4, w_k2 = tid & 15;   // W: g row, float2 at k = w_k2*2
    // compute mapping
    int gl0 = (tid & 15) * 2;               // 2 g columns
    int b0  = (tid >> 4) * 2;               // 1 b-pair

    unsigned long long accI0 = 0ull, accI1 = 0ull, accH0 = 0ull, accH1 = 0ull;

    // chunk load helpers (c in [0,48): c<16 -> x/Wih K=c*32; else h/Whh K=(c-16)*32)
    #define GRU_LOAD(c, ra, rw) { \
        if ((c) < 16) { \
            ra = *(const float4*)&emb[(size_t)sIdx[a_b] * D + (c) * 32 + a_kq * 4]; \
            rw = *(const float2*)&Wih[(size_t)(g0 + w_g) * D + (c) * 32 + w_k2 * 2]; \
        } else { \
            ra = *(const float4*)&hin[a_b * H + ((c) - 16) * 32 + a_kq * 4]; \
            rw = *(const float2*)&Whh[(size_t)(g0 + w_g) * H + ((c) - 16) * 32 + w_k2 * 2]; \
        } }
    #define GRU_STORE(buf, ra, rw) { \
        sA[buf][a_kq * 4 + 0][a_b] = ra.x; \
        sA[buf][a_kq * 4 + 1][a_b] = ra.y; \
        sA[buf][a_kq * 4 + 2][a_b] = ra.z; \
        sA[buf][a_kq * 4 + 3][a_b] = ra.w; \
        sWd[buf][w_k2 * 2 + 0][w_g] = pack2(rw.x, rw.x); \
        sWd[buf][w_k2 * 2 + 1][w_g] = pack2(rw.y, rw.y); }

    {
        float4 ra; float2 rw;
        GRU_LOAD(0, ra, rw);
        GRU_STORE(0, ra, rw);
    }
    __syncthreads();

    #define GRU_CHUNK(c, ACC0, ACC1) { \
        int cur = (c) & 1; \
        float4 nra = make_float4(0.f,0.f,0.f,0.f); float2 nrw = make_float2(0.f,0.f); \
        bool more = (c) + 1 < 48; \
        if (more) { GRU_LOAD((c) + 1, nra, nrw); } \
        _Pragma("unroll") \
        for (int kk = 0; kk < 32; kk++) { \
            unsigned long long a2 = *(const unsigned long long*)&sA[cur][kk][b0]; \
            ulonglong2 wd = *(const ulonglong2*)&sWd[cur][kk][gl0]; \
            fma2(ACC0, a2, wd.x); \
            fma2(ACC1, a2, wd.y); \
        } \
        if (more) { GRU_STORE(cur ^ 1, nra, nrw); } \
        __syncthreads(); }

    for (int c = 0; c < 16; c++)  GRU_CHUNK(c, accI0, accI1);
    for (int c = 16; c < 48; c++) GRU_CHUNK(c, accH0, accH1);

    #undef GRU_CHUNK
    #undef GRU_STORE
    #undef GRU_LOAD

    // epilogue: scatter 8 floats (bias folded into gate kernel-free form: store raw, gate adds nothing here;
    // biases are zeros in this problem but we must honor them generally -> fold in gate kernel instead?
    // Keep exact: biases added in gate kernel would change math order vs reference (gi = x@W^T + b).
    // Adding b here after accumulation matches reference exactly.)
    {
        int g = g0 + gl0;
        float2 fi0 = unpack2(accI0), fi1 = unpack2(accI1);
        float2 fh0 = unpack2(accH0), fh1 = unpack2(accH1);
        g_gi[b0 * G3 + g]           = fi0.x;
        g_gi[(b0 + 1) * G3 + g]     = fi0.y;
        g_gi[b0 * G3 + g + 1]       = fi1.x;
        g_gi[(b0 + 1) * G3 + g + 1] = fi1.y;
        g_gh[b0 * G3 + g]           = fh0.x;
        g_gh[(b0 + 1) * G3 + g]     = fh0.y;
        g_gh[b0 * G3 + g + 1]       = fh1.x;
        g_gh[(b0 + 1) * G3 + g + 1] = fh1.y;
    }
}

// ---------------- gate update + bias + packed reset ----------------
__global__ void __launch_bounds__(256) gru_gate_kernel(
    int t, const float* __restrict__ seq_emb,
    const float* __restrict__ bih, const float* __restrict__ bhh)
{
    int id = blockIdx.x * 256 + threadIdx.x;   // 65536 threads
    int b = id >> 10, j = id & 1023;
    const float* hin = (t == 0) ? seq_emb : g_h;
    float ir = g_gi[b * G3 + j]        + bih[j];
    float hr = g_gh[b * G3 + j]        + bhh[j];
    float iz = g_gi[b * G3 + 1024 + j] + bih[1024 + j];
    float hz = g_gh[b * G3 + 1024 + j] + bhh[1024 + j];
    float inn= g_gi[b * G3 + 2048 + j] + bih[2048 + j];
    float hn = g_gh[b * G3 + 2048 + j] + bhh[2048 + j];
    float r = 1.f / (1.f + expf(-(ir + hr)));
    float z = 1.f / (1.f + expf(-(iz + hz)));
    float n = tanhf(inn + r * hn);
    float h = (1.f - z) * n + z * hin[b * H + j];
    g_h[b * H + j] = h;
    if (id < B) g_packed[id] = 0ull;
}

// ============================================================================
// Logits GEMM v2 + gumbel + argmax.
// Grid 125 x 512 threads (one flat wave). Block tile 64 b x 256 v, K=1024 in
// 64 chunks of 16. Double-buffered; w duplicated as u64 in smem;
// lane-contiguous LDS.128 reads (conflict-free).
// Thread: 4 b (b0 = warp*4) x 8 v (v = 64q + 2*lane + j, q=0..3, j=0..1).
// Inner per kk: 1 LDS.128 (a, broadcast) + 4 LDS.128 (w) + 16 FMA2.
// ============================================================================
#define LG_WROW 260                      // u64 per sWd row (256 + pad)
#define LG_SWD_BYTES (2 * 16 * LG_WROW * 8)
#define LG_SH_BYTES  (2 * 16 * 68 * 4)
#define LG_SMEM      (LG_SWD_BYTES + LG_SH_BYTES)

__global__ void __launch_bounds__(512) logits_kernel(
    int t, const float* __restrict__ fcw, const float* __restrict__ fcb,
    float* __restrict__ out, uint32_t k0, uint32_t k1)
{
    extern __shared__ unsigned char smraw[];
    unsigned long long* sWdB = (unsigned long long*)smraw;           // [2][16][LG_WROW]
    float* sHB = (float*)(smraw + LG_SWD_BYTES);                     // [2][16][68]
    #define SWD(buf, k, v) sWdB[(((buf) * 16 + (k)) * LG_WROW) + (v)]
    #define SH(buf, k, b)  sHB[(((buf) * 16 + (k)) * 68) + (b)]

    int tid = threadIdx.x;
    int vblk = blockIdx.x * 256;
    int lane = tid & 31;
    int wid  = tid >> 5;
    int b0   = wid * 4;

    // load-phase mapping
    int w_v = tid >> 1, w_kh = (tid & 1) * 8;   // w: v row, 8 k starting at w_kh
    int h_b = tid >> 3, h_k2 = tid & 7;         // h: b row, float2 at k = h_k2*2

    unsigned long long acc[4][2][2];
    #pragma unroll
    for (int q = 0; q < 4; q++)
        #pragma unroll
        for (int j = 0; j < 2; j++) { acc[q][j][0] = 0ull; acc[q][j][1] = 0ull; }

    #define LG_LOAD(c, rw0, rw1, rh) { \
        const float* wp = &fcw[(size_t)(vblk + w_v) * H + (c) * 16 + w_kh]; \
        rw0 = *(const float4*)wp; \
        rw1 = *(const float4*)(wp + 4); \
        rh  = *(const float2*)&g_h[h_b * H + (c) * 16 + h_k2 * 2]; }
    #define LG_STORE(buf, rw0, rw1, rh) { \
        SWD(buf, w_kh + 0, w_v) = pack2(rw0.x, rw0.x); \
        SWD(buf, w_kh + 1, w_v) = pack2(rw0.y, rw0.y); \
        SWD(buf, w_kh + 2, w_v) = pack2(rw0.z, rw0.z); \
        SWD(buf, w_kh + 3, w_v) = pack2(rw0.w, rw0.w); \
        SWD(buf, w_kh + 4, w_v) = pack2(rw1.x, rw1.x); \
        SWD(buf, w_kh + 5, w_v) = pack2(rw1.y, rw1.y); \
        SWD(buf, w_kh + 6, w_v) = pack2(rw1.z, rw1.z); \
        SWD(buf, w_kh + 7, w_v) = pack2(rw1.w, rw1.w); \
        SH(buf, h_k2 * 2 + 0, h_b) = rh.x; \
        SH(buf, h_k2 * 2 + 1, h_b) = rh.y; }

    {
        float4 rw0, rw1; float2 rh;
        LG_LOAD(0, rw0, rw1, rh);
        LG_STORE(0, rw0, rw1, rh);
    }
    __syncthreads();

    for (int c = 0; c < 64; c++) {
        int cur = c & 1;
        float4 nrw0 = make_float4(0.f,0.f,0.f,0.f), nrw1 = make_float4(0.f,0.f,0.f,0.f);
        float2 nrh = make_float2(0.f,0.f);
        bool more = (c + 1 < 64);
        if (more) { LG_LOAD(c + 1, nrw0, nrw1, nrh); }
        #pragma unroll
        for (int kk = 0; kk < 16; kk++) {
            ulonglong2 a = *(const ulonglong2*)&SH(cur, kk, b0);
            #pragma unroll
            for (int q = 0; q < 4; q++) {
                ulonglong2 w = *(const ulonglong2*)&SWD(cur, kk, q * 64 + lane * 2);
                fma2(acc[q][0][0], a.x, w.x); fma2(acc[q][0][1], a.y, w.x);
                fma2(acc[q][1][0], a.x, w.y); fma2(acc[q][1][1], a.y, w.y);
            }
        }
        if (more) { LG_STORE(cur ^ 1, nrw0, nrw1, nrh); }
        __syncthreads();
    }
    #undef LG_STORE
    #undef LG_LOAD

    // unpack: vals[bi][q][j], bi = 0..3 -> b = b0+bi, v = vblk + q*64 + 2*lane + j
    float vals[4][4][2];
    #pragma unroll
    for (int q = 0; q < 4; q++) {
        float2 bias = *(const float2*)&fcb[vblk + q * 64 + lane * 2];
        #pragma unroll
        for (int j = 0; j < 2; j++) {
            float bj = (j == 0) ? bias.x : bias.y;
            float2 f0 = unpack2(acc[q][j][0]);   // b0, b0+1
            float2 f1 = unpack2(acc[q][j][1]);   // b0+2, b0+3
            vals[0][q][j] = f0.x + bj;
            vals[1][q][j] = f0.y + bj;
            vals[2][q][j] = f1.x + bj;
            vals[3][q][j] = f1.y + bj;
        }
    }

    float* outL = out + 3200 + (size_t)t * (B * V);
    #pragma unroll
    for (int bi = 0; bi < 4; bi++) {
        int b = b0 + bi;
        #pragma unroll
        for (int q = 0; q < 4; q++) {
            float2 st = make_float2(vals[bi][q][0], vals[bi][q][1]);
            *(float2*)&outL[(size_t)b * V + vblk + q * 64 + lane * 2] = st;
        }
    }

    // Gumbel-max epilogue. JAX partitionable threefry: bits[i] = o0^o1 of tf(key,(0,i)), i = b*V+v.
    #pragma unroll
    for (int bi = 0; bi < 4; bi++) {
        int b = b0 + bi;
        unsigned long long p = 0ull;
        #pragma unroll
        for (int q = 0; q < 4; q++) {
            #pragma unroll
            for (int j = 0; j < 2; j++) {
                int vg = vblk + q * 64 + lane * 2 + j;
                unsigned cnt = (unsigned)(b * V + vg);
                uint32_t o0, o1;
                tf2x32(k0, k1, 0u, cnt, o0, o1);
                uint32_t bits = o0 ^ o1;
                float f = __uint_as_float((bits >> 9) | 0x3f800000u) - 1.0f;
                float u = fmaxf(f, 1.17549435e-38f);
                float gmb = -logf(-logf(u));
                float val = vals[bi][q][j] + gmb;
                unsigned s = __float_as_uint(val);
                unsigned ord = (s & 0x80000000u) ? ~s : (s | 0x80000000u);
                unsigned long long pj = ((unsigned long long)ord << 32)
                                      | (unsigned long long)(0x7FFFFFFFu - (unsigned)vg);
                if (pj > p) p = pj;
            }
        }
        #pragma unroll
        for (int off = 16; off; off >>= 1) {
            unsigned long long q2 = __shfl_down_sync(0xFFFFFFFFu, p, off);
            if (q2 > p) p = q2;
        }
        if (lane == 0) atomicMax(&g_packed[b], p);
    }
    #undef SWD
    #undef SH
}

// ---------------- final sample: packed -> index output (t = T-1 only) ----------------
__global__ void sample_kernel(int t, float* __restrict__ out) {
    int b = threadIdx.x;
    unsigned long long p = g_packed[b];
    int v = (int)(0x7FFFFFFFu - (unsigned)(p & 0xFFFFFFFFull));
    out[t * B + b] = (float)v;
}

// ---------------- launch ----------------
extern "C" void kernel_launch(void* const* d_in, const int* in_sizes, int n_in,
                              void* d_out, int out_size) {
    (void)in_sizes; (void)n_in; (void)out_size;
    const float* seq = (const float*)d_in[0];
    const float* emb = (const float*)d_in[1];
    const float* Wih = (const float*)d_in[2];
    const float* Whh = (const float*)d_in[3];
    const float* bih = (const float*)d_in[4];
    const float* bhh = (const float*)d_in[5];
    const float* fcw = (const float*)d_in[6];
    const float* fcb = (const float*)d_in[7];
    const int*   eos = (const int*)d_in[8];
    float* out = (float*)d_out;

    cudaFuncSetAttribute(logits_kernel, cudaFuncAttributeMaxDynamicSharedMemorySize, LG_SMEM);

    // keys: jax.random.split(key(42), 50), partitionable (fold-like):
    // key_t = threefry2x32((0,42), (0, t))
    uint32_t keys[T][2];
    for (int t = 0; t < T; t++) {
        uint32_t a, b;
        tf2x32_host(0u, 42u, 0u, (uint32_t)t, &a, &b);
        keys[t][0] = a; keys[t][1] = b;
    }

    for (int t = 0; t < T; t++) {
        gru_gemm_kernel<<<96, 512>>>(t, seq, emb, Wih, Whh, eos, out);
        gru_gate_kernel<<<256, 256>>>(t, seq, bih, bhh);
        logits_kernel<<<125, 512, LG_SMEM>>>(t, fcw, fcb, out, keys[t][0], keys[t][1]);
    }
    sample_kernel<<<1, 64>>>(T - 1, out);
}

// round 8
// speedup vs baseline: 1.3772x; 1.3772x over previous
#include <cuda_runtime.h>
#include <cstdint>

#define B 64
#define T 50
#define D 512
#define H 1024
#define V 32000
#define G3 3072   // 3*H

// ---------------- scratch (no allocations allowed) ----------------
__device__ float g_h[B * H];
__device__ float g_gi[B * G3];
__device__ float g_ghA[B * G3];
__device__ float g_ghB[B * G3];
__device__ unsigned long long g_packed[B];

// ---------------- packed f32x2 helpers (sm_100a) ----------------
__device__ __forceinline__ void fma2(unsigned long long& d, unsigned long long a, unsigned long long b) {
    asm("fma.rn.f32x2 %0, %1, %2, %0;" : "+l"(d) : "l"(a), "l"(b));
}
__device__ __forceinline__ unsigned long long pack2(float x, float y) {
    unsigned long long r; asm("mov.b64 %0, {%1, %2};" : "=l"(r) : "f"(x), "f"(y)); return r;
}
__device__ __forceinline__ float2 unpack2(unsigned long long v) {
    float2 r; asm("mov.b64 {%0, %1}, %2;" : "=f"(r.x), "=f"(r.y) : "l"(v)); return r;
}

// ---------------- threefry2x32 (exact JAX rotation/key schedule) ----------------
__device__ __forceinline__ void tf2x32(uint32_t k0, uint32_t k1, uint32_t x0, uint32_t x1,
                                       uint32_t& o0, uint32_t& o1) {
    uint32_t ks2 = k0 ^ k1 ^ 0x1BD11BDAu;
    x0 += k0; x1 += k1;
#define RND(r) { x0 += x1; x1 = __funnelshift_l(x1, x1, (r)); x1 ^= x0; }
    RND(13) RND(15) RND(26) RND(6)   x0 += k1;  x1 += ks2 + 1u;
    RND(17) RND(29) RND(16) RND(24)  x0 += ks2; x1 += k0  + 2u;
    RND(13) RND(15) RND(26) RND(6)   x0 += k0;  x1 += k1  + 3u;
    RND(17) RND(29) RND(16) RND(24)  x0 += k1;  x1 += ks2 + 4u;
    RND(13) RND(15) RND(26) RND(6)   x0 += ks2; x1 += k0  + 5u;
#undef RND
    o0 = x0; o1 = x1;
}

static inline uint32_t h_rotl(uint32_t v, int d) { return (v << d) | (v >> (32 - d)); }
static void tf2x32_host(uint32_t k0, uint32_t k1, uint32_t x0, uint32_t x1,
                        uint32_t* o0, uint32_t* o1) {
    uint32_t ks2 = k0 ^ k1 ^ 0x1BD11BDAu;
    const int rA[4] = {13, 15, 26, 6}, rB[4] = {17, 29, 16, 24};
    x0 += k0; x1 += k1;
    for (int i = 0; i < 4; i++) { x0 += x1; x1 = h_rotl(x1, rA[i]); x1 ^= x0; }
    x0 += k1;  x1 += ks2 + 1u;
    for (int i = 0; i < 4; i++) { x0 += x1; x1 = h_rotl(x1, rB[i]); x1 ^= x0; }
    x0 += ks2; x1 += k0 + 2u;
    for (int i = 0; i < 4; i++) { x0 += x1; x1 = h_rotl(x1, rA[i]); x1 ^= x0; }
    x0 += k0;  x1 += k1 + 3u;
    for (int i = 0; i < 4; i++) { x0 += x1; x1 = h_rotl(x1, rB[i]); x1 ^= x0; }
    x0 += k1;  x1 += ks2 + 4u;
    for (int i = 0; i < 4; i++) { x0 += x1; x1 = h_rotl(x1, rA[i]); x1 ^= x0; }
    x0 += ks2; x1 += k0 + 5u;
    *o0 = x0; *o1 = x1;
}

// ============================================================================
// GRU gemm v3: k-split x2. Grid 192 = 96 g-tiles x 2 K-parts, 512 threads.
// part 0: x@Wih^T (K=512, chunks 0..15) + h[0:256]@Whh^T (chunks 16..23) -> g_gi, g_ghA
// part 1: h[256:1024]@Whh^T (chunks 24..47)                              -> g_ghB
// Double-buffered smem; W duplicated as u64 (issue-optimal 8-slot inner loop).
// Block 0 also writes out sampled indices of step t-1.
// ============================================================================
__global__ void __launch_bounds__(512) gru_gemm_kernel(
    int t, const float* __restrict__ seq_emb, const float* __restrict__ emb,
    const float* __restrict__ Wih, const float* __restrict__ Whh,
    const int* __restrict__ eosp, float* __restrict__ out)
{
    __shared__ float sA[2][32][68];
    __shared__ unsigned long long sWd[2][32][34];
    __shared__ int sIdx[B];
    int tid = threadIdx.x;
    int bx = blockIdx.x;
    int part = (bx >= 96) ? 1 : 0;
    int g0 = (part ? bx - 96 : bx) * 32;

    if (tid < B) {
        int idx;
        if (t == 0) idx = eosp[0];
        else idx = (int)(0x7FFFFFFFu - (unsigned)(g_packed[tid] & 0xFFFFFFFFull));
        sIdx[tid] = idx;
        if (bx == 0 && t > 0) out[(t - 1) * B + tid] = (float)idx;
    }
    __syncthreads();

    const float* hin = (t == 0) ? seq_emb : g_h;

    // load-phase mapping
    int a_b  = tid >> 3, a_kq = tid & 7;    // A: b row, float4 at k = a_kq*4
    int w_g  = tid >> 4, w_k2 = tid & 15;   // W: g row, float2 at k = w_k2*2
    // compute mapping: 2 g cols x 1 b-pair per thread
    int gl0 = (tid & 15) * 2;
    int b0  = (tid >> 4) * 2;

    unsigned long long accI0 = 0ull, accI1 = 0ull, accH0 = 0ull, accH1 = 0ull;

    int cbeg = part ? 24 : 0;
    int cend = part ? 48 : 24;

    // chunk c: c<16 -> x/Wih at k=c*32; else -> h/Whh at k=(c-16)*32
    #define GRU_LOAD(c, ra, rw) { \
        if ((c) < 16) { \
            ra = *(const float4*)&emb[(size_t)sIdx[a_b] * D + (c) * 32 + a_kq * 4]; \
            rw = *(const float2*)&Wih[(size_t)(g0 + w_g) * D + (c) * 32 + w_k2 * 2]; \
        } else { \
            ra = *(const float4*)&hin[a_b * H + ((c) - 16) * 32 + a_kq * 4]; \
            rw = *(const float2*)&Whh[(size_t)(g0 + w_g) * H + ((c) - 16) * 32 + w_k2 * 2]; \
        } }
    #define GRU_STORE(buf, ra, rw) { \
        sA[buf][a_kq * 4 + 0][a_b] = ra.x; \
        sA[buf][a_kq * 4 + 1][a_b] = ra.y; \
        sA[buf][a_kq * 4 + 2][a_b] = ra.z; \
        sA[buf][a_kq * 4 + 3][a_b] = ra.w; \
        sWd[buf][w_k2 * 2 + 0][w_g] = pack2(rw.x, rw.x); \
        sWd[buf][w_k2 * 2 + 1][w_g] = pack2(rw.y, rw.y); }

    {
        float4 ra; float2 rw;
        GRU_LOAD(cbeg, ra, rw);
        GRU_STORE(0, ra, rw);
    }
    __syncthreads();

    for (int c = cbeg; c < cend; c++) {
        int cur = (c - cbeg) & 1;
        float4 nra = make_float4(0.f,0.f,0.f,0.f); float2 nrw = make_float2(0.f,0.f);
        bool more = (c + 1 < cend);
        if (more) { GRU_LOAD(c + 1, nra, nrw); }
        bool isX = (c < 16);
        if (isX) {
            #pragma unroll
            for (int kk = 0; kk < 32; kk++) {
                unsigned long long a2 = *(const unsigned long long*)&sA[cur][kk][b0];
                ulonglong2 wd = *(const ulonglong2*)&sWd[cur][kk][gl0];
                fma2(accI0, a2, wd.x);
                fma2(accI1, a2, wd.y);
            }
        } else {
            #pragma unroll
            for (int kk = 0; kk < 32; kk++) {
                unsigned long long a2 = *(const unsigned long long*)&sA[cur][kk][b0];
                ulonglong2 wd = *(const ulonglong2*)&sWd[cur][kk][gl0];
                fma2(accH0, a2, wd.x);
                fma2(accH1, a2, wd.y);
            }
        }
        if (more) { GRU_STORE(cur ^ 1, nra, nrw); }
        __syncthreads();
    }
    #undef GRU_STORE
    #undef GRU_LOAD

    {
        int g = g0 + gl0;
        float2 fh0 = unpack2(accH0), fh1 = unpack2(accH1);
        float* gh = part ? g_ghB : g_ghA;
        gh[b0 * G3 + g]           = fh0.x;
        gh[(b0 + 1) * G3 + g]     = fh0.y;
        gh[b0 * G3 + g + 1]       = fh1.x;
        gh[(b0 + 1) * G3 + g + 1] = fh1.y;
        if (part == 0) {
            float2 fi0 = unpack2(accI0), fi1 = unpack2(accI1);
            g_gi[b0 * G3 + g]           = fi0.x;
            g_gi[(b0 + 1) * G3 + g]     = fi0.y;
            g_gi[b0 * G3 + g + 1]       = fi1.x;
            g_gi[(b0 + 1) * G3 + g + 1] = fi1.y;
        }
    }
}

// ---------------- gate update + bias + partial-sum + packed reset ----------------
__global__ void __launch_bounds__(256) gru_gate_kernel(
    int t, const float* __restrict__ seq_emb,
    const float* __restrict__ bih, const float* __restrict__ bhh)
{
    int id = blockIdx.x * 256 + threadIdx.x;   // 65536 threads
    int b = id >> 10, j = id & 1023;
    const float* hin = (t == 0) ? seq_emb : g_h;
    float ir = g_gi[b * G3 + j]                                  + bih[j];
    float hr = g_ghA[b * G3 + j]        + g_ghB[b * G3 + j]      + bhh[j];
    float iz = g_gi[b * G3 + 1024 + j]                           + bih[1024 + j];
    float hz = g_ghA[b * G3 + 1024 + j] + g_ghB[b * G3 + 1024+j] + bhh[1024 + j];
    float inn= g_gi[b * G3 + 2048 + j]                           + bih[2048 + j];
    float hn = g_ghA[b * G3 + 2048 + j] + g_ghB[b * G3 + 2048+j] + bhh[2048 + j];
    float r = 1.f / (1.f + expf(-(ir + hr)));
    float z = 1.f / (1.f + expf(-(iz + hz)));
    float n = tanhf(inn + r * hn);
    float h = (1.f - z) * n + z * hin[b * H + j];
    g_h[b * H + j] = h;
    if (id < B) g_packed[id] = 0ull;
}

// ============================================================================
// Logits GEMM v3 + gumbel + argmax. Grid 125 x 512 threads (one flat wave).
// Block tile 64 b x 256 v, K=1024 in 64 chunks of 16. Double-buffered.
// Warp = 8 b x 128 v: all lanes share the b-octet -> a-LDS is pure broadcast
// (free on the crossbar); w read natural float4, duplicated via reg MOVs.
// Thread: 8 b (4 pairs) x 4 v. Inner per kk: 2 bcast LDS.128 (a) +
// 1 LDS.128 (w, conflict-free) + 4 packs + 16 FMA2.
// ============================================================================
__global__ void __launch_bounds__(512) logits_kernel(
    int t, const float* __restrict__ fcw, const float* __restrict__ fcb,
    float* __restrict__ out, uint32_t k0, uint32_t k1)
{
    __shared__ float sW[2][16][260];   // [buf][k][v] natural floats, pitch 260 (1040B = 65*16)
    __shared__ float sH[2][16][68];    // [buf][k][b], pitch 272B = 17*16

    int tid = threadIdx.x;
    int vblk = blockIdx.x * 256;
    int lane = tid & 31;
    int wid  = tid >> 5;
    int b0    = (wid >> 1) * 8;            // 8 b per warp
    int vbase = (wid & 1) * 128 + lane * 4; // 4 v per thread

    // load-phase mapping
    int w_v = tid >> 1, w_kh = (tid & 1) * 8;   // w: v row, 8 k from w_kh
    int h_b = tid >> 3, h_k2 = tid & 7;         // h: b row, float2 at k = h_k2*2

    // acc[vj][bpair]: b = b0 + 2*bp + {lo,hi}
    unsigned long long acc[4][4];
    #pragma unroll
    for (int j = 0; j < 4; j++)
        #pragma unroll
        for (int p = 0; p < 4; p++) acc[j][p] = 0ull;

    #define LG_LOAD(c, rw0, rw1, rh) { \
        const float* wp = &fcw[(size_t)(vblk + w_v) * H + (c) * 16 + w_kh]; \
        rw0 = *(const float4*)wp; \
        rw1 = *(const float4*)(wp + 4); \
        rh  = *(const float2*)&g_h[h_b * H + (c) * 16 + h_k2 * 2]; }
    #define LG_STORE(buf, rw0, rw1, rh) { \
        sW[buf][w_kh + 0][w_v] = rw0.x; \
        sW[buf][w_kh + 1][w_v] = rw0.y; \
        sW[buf][w_kh + 2][w_v] = rw0.z; \
        sW[buf][w_kh + 3][w_v] = rw0.w; \
        sW[buf][w_kh + 4][w_v] = rw1.x; \
        sW[buf][w_kh + 5][w_v] = rw1.y; \
        sW[buf][w_kh + 6][w_v] = rw1.z; \
        sW[buf][w_kh + 7][w_v] = rw1.w; \
        sH[buf][h_k2 * 2 + 0][h_b] = rh.x; \
        sH[buf][h_k2 * 2 + 1][h_b] = rh.y; }

    {
        float4 rw0, rw1; float2 rh;
        LG_LOAD(0, rw0, rw1, rh);
        LG_STORE(0, rw0, rw1, rh);
    }
    __syncthreads();

    for (int c = 0; c < 64; c++) {
        int cur = c & 1;
        float4 nrw0 = make_float4(0.f,0.f,0.f,0.f), nrw1 = make_float4(0.f,0.f,0.f,0.f);
        float2 nrh = make_float2(0.f,0.f);
        bool more = (c + 1 < 64);
        if (more) { LG_LOAD(c + 1, nrw0, nrw1, nrh); }
        #pragma unroll
        for (int kk = 0; kk < 16; kk++) {
            ulonglong2 aA = *(const ulonglong2*)&sH[cur][kk][b0];       // b0..b0+3 (broadcast)
            ulonglong2 aB = *(const ulonglong2*)&sH[cur][kk][b0 + 4];   // b0+4..b0+7 (broadcast)
            float4 w = *(const float4*)&sW[cur][kk][vbase];             // conflict-free
            unsigned long long w0 = pack2(w.x, w.x);
            unsigned long long w1 = pack2(w.y, w.y);
            unsigned long long w2 = pack2(w.z, w.z);
            unsigned long long w3 = pack2(w.w, w.w);
            fma2(acc[0][0], aA.x, w0); fma2(acc[0][1], aA.y, w0);
            fma2(acc[0][2], aB.x, w0); fma2(acc[0][3], aB.y, w0);
            fma2(acc[1][0], aA.x, w1); fma2(acc[1][1], aA.y, w1);
            fma2(acc[1][2], aB.x, w1); fma2(acc[1][3], aB.y, w1);
            fma2(acc[2][0], aA.x, w2); fma2(acc[2][1], aA.y, w2);
            fma2(acc[2][2], aB.x, w2); fma2(acc[2][3], aB.y, w2);
            fma2(acc[3][0], aA.x, w3); fma2(acc[3][1], aA.y, w3);
            fma2(acc[3][2], aB.x, w3); fma2(acc[3][3], aB.y, w3);
        }
        if (more) { LG_STORE(cur ^ 1, nrw0, nrw1, nrh); }
        __syncthreads();
    }
    #undef LG_STORE
    #undef LG_LOAD

    // unpack: vals[bi][j], bi = 0..7 -> b = b0+bi, v = vblk + vbase + j
    float vals[8][4];
    float4 bias = *(const float4*)&fcb[vblk + vbase];
    #pragma unroll
    for (int j = 0; j < 4; j++) {
        float bj = (j == 0) ? bias.x : (j == 1) ? bias.y : (j == 2) ? bias.z : bias.w;
        #pragma unroll
        for (int p = 0; p < 4; p++) {
            float2 f = unpack2(acc[j][p]);
            vals[2 * p][j]     = f.x + bj;
            vals[2 * p + 1][j] = f.y + bj;
        }
    }

    float* outL = out + 3200 + (size_t)t * (B * V);
    #pragma unroll
    for (int bi = 0; bi < 8; bi++) {
        int b = b0 + bi;
        float4 st = make_float4(vals[bi][0], vals[bi][1], vals[bi][2], vals[bi][3]);
        *(float4*)&outL[(size_t)b * V + vblk + vbase] = st;
    }

    // Gumbel-max epilogue. JAX partitionable threefry: bits[i] = o0^o1 of tf(key,(0,i)), i = b*V+v.
    #pragma unroll
    for (int bi = 0; bi < 8; bi++) {
        int b = b0 + bi;
        unsigned long long p = 0ull;
        #pragma unroll
        for (int j = 0; j < 4; j++) {
            int vg = vblk + vbase + j;
            unsigned cnt = (unsigned)(b * V + vg);
            uint32_t o0, o1;
            tf2x32(k0, k1, 0u, cnt, o0, o1);
            uint32_t bits = o0 ^ o1;
            float f = __uint_as_float((bits >> 9) | 0x3f800000u) - 1.0f;
            float u = fmaxf(f, 1.17549435e-38f);
            float gmb = -logf(-logf(u));
            float val = vals[bi][j] + gmb;
            unsigned s = __float_as_uint(val);
            unsigned ord = (s & 0x80000000u) ? ~s : (s | 0x80000000u);
            unsigned long long pj = ((unsigned long long)ord << 32)
                                  | (unsigned long long)(0x7FFFFFFFu - (unsigned)vg);
            if (pj > p) p = pj;
        }
        #pragma unroll
        for (int off = 16; off; off >>= 1) {
            unsigned long long q2 = __shfl_down_sync(0xFFFFFFFFu, p, off);
            if (q2 > p) p = q2;
        }
        if (lane == 0) atomicMax(&g_packed[b], p);
    }
}

// ---------------- final sample: packed -> index output (t = T-1 only) ----------------
__global__ void sample_kernel(int t, float* __restrict__ out) {
    int b = threadIdx.x;
    unsigned long long p = g_packed[b];
    int v = (int)(0x7FFFFFFFu - (unsigned)(p & 0xFFFFFFFFull));
    out[t * B + b] = (float)v;
}

// ---------------- launch ----------------
extern "C" void kernel_launch(void* const* d_in, const int* in_sizes, int n_in,
                              void* d_out, int out_size) {
    (void)in_sizes; (void)n_in; (void)out_size;
    const float* seq = (const float*)d_in[0];
    const float* emb = (const float*)d_in[1];
    const float* Wih = (const float*)d_in[2];
    const float* Whh = (const float*)d_in[3];
    const float* bih = (const float*)d_in[4];
    const float* bhh = (const float*)d_in[5];
    const float* fcw = (const float*)d_in[6];
    const float* fcb = (const float*)d_in[7];
    const int*   eos = (const int*)d_in[8];
    float* out = (float*)d_out;

    // keys: jax.random.split(key(42), 50), partitionable (fold-like):
    // key_t = threefry2x32((0,42), (0, t))
    uint32_t keys[T][2];
    for (int t = 0; t < T; t++) {
        uint32_t a, b;
        tf2x32_host(0u, 42u, 0u, (uint32_t)t, &a, &b);
        keys[t][0] = a; keys[t][1] = b;
    }

    for (int t = 0; t < T; t++) {
        gru_gemm_kernel<<<192, 512>>>(t, seq, emb, Wih, Whh, eos, out);
        gru_gate_kernel<<<256, 256>>>(t, seq, bih, bhh);
        logits_kernel<<<125, 512>>>(t, fcw, fcb, out, keys[t][0], keys[t][1]);
    }
    sample_kernel<<<1, 64>>>(T - 1, out);
}